// round 17
// baseline (speedup 1.0000x reference)
#include <cuda_runtime.h>
#include <cstdint>

// YOLO detection decode: x (64, 255, 52, 52) f32 -> out (64, 8112, 85) f32
// v9-family (converged; best bench 56.1us, DRAM ~72%).
// This round's single A/B: default-policy STG instead of __stcs.
//   __stcs marks output lines evict-first -> eager writeback bursts competing
//   with the read stream on the 72%-busy DRAM interface. Default policy lets
//   L2 (126MB) buffer the write set and drain it between read bursts.
//   (Load-side twin __ldcs was a measured loss, removed in R9 for +3.8us.)
// All other structure identical to the converged optimum:
//   - 9984 small independent blocks, 256 thr, one 52-row tile per block
//   - batched 4+1 LDG.128 per thread (MLP=5), default-cached
//   - tanh.approx sigmoid (1 MUFU), exp only for w/h channels
//   - scalar-STS transpose into output-layout smem
//   - contiguous float4 STG of the tile's 17680B output span

#define G 52
#define GG 2704              // G*G
#define GGV 676              // GG/4 (channel stride in float4)
#define IN_PER_B 689520      // 255*GG
#define NE 85
#define TILE 52
#define QV 13                // TILE/4
#define NV (NE * QV)         // 1105 float4 per tile
#define TILES_PER_PLANE 52
#define THREADS 256

__constant__ float c_aw[3] = {10.0f, 16.0f, 33.0f};
__constant__ float c_ah[3] = {13.0f, 30.0f, 23.0f};

__device__ __forceinline__ float fsigmoid(float v) {
    // sigmoid(v) = 0.5 + 0.5*tanh(0.5*v); MUFU.TANH, abs err ~2^-12
    float t;
    asm("tanh.approx.f32 %0, %1;" : "=f"(t) : "f"(0.5f * v));
    return fmaf(0.5f, t, 0.5f);
}

__device__ __forceinline__ void transform_store(
    float* __restrict__ s, float4 v, int j, int p0, float aw, float ah) {
    const int e = j / QV;
    const int q = j - e * QV;
    const int lp = q * 4;

    float o0, o1, o2, o3;
    if (e >= 4) {
        o0 = fsigmoid(v.x); o1 = fsigmoid(v.y);
        o2 = fsigmoid(v.z); o3 = fsigmoid(v.w);
    } else if (e == 0) {
        const int p = p0 + lp;
        o0 = (fsigmoid(v.x) + (float)((p    ) % G)) * 8.0f;
        o1 = (fsigmoid(v.y) + (float)((p + 1) % G)) * 8.0f;
        o2 = (fsigmoid(v.z) + (float)((p + 2) % G)) * 8.0f;
        o3 = (fsigmoid(v.w) + (float)((p + 3) % G)) * 8.0f;
    } else if (e == 1) {
        const int p = p0 + lp;
        o0 = (fsigmoid(v.x) + (float)((p    ) / G)) * 8.0f;
        o1 = (fsigmoid(v.y) + (float)((p + 1) / G)) * 8.0f;
        o2 = (fsigmoid(v.z) + (float)((p + 2) / G)) * 8.0f;
        o3 = (fsigmoid(v.w) + (float)((p + 3) / G)) * 8.0f;
    } else if (e == 2) {
        o0 = __expf(v.x) * aw; o1 = __expf(v.y) * aw;
        o2 = __expf(v.z) * aw; o3 = __expf(v.w) * aw;
    } else { // e == 3
        o0 = __expf(v.x) * ah; o1 = __expf(v.y) * ah;
        o2 = __expf(v.z) * ah; o3 = __expf(v.w) * ah;
    }
    float* sp = s + lp * NE + e;     // output layout: word = lp*85 + e
    sp[0 * NE] = o0; sp[1 * NE] = o1; sp[2 * NE] = o2; sp[3 * NE] = o3;
}

__global__ __launch_bounds__(THREADS, 8)
void det_decode_kernel(const float* __restrict__ x, float* __restrict__ out) {
    __shared__ alignas(128) float s[TILE * NE];   // 17,680 B

    // Tile -> (b, a, p0). tiles/anchor = 52, tiles/batch = 156.
    const int t   = blockIdx.x;
    const int b   = t / 156;
    const int rem = t - b * 156;
    const int a   = rem / TILES_PER_PLANE;
    const int pt  = rem - a * TILES_PER_PLANE;
    const int p0  = pt * TILE;

    const float4* __restrict__ src = reinterpret_cast<const float4*>(
        x + (size_t)b * IN_PER_B + (size_t)(a * NE) * GG + p0);

    const float aw = c_aw[a];
    const float ah = c_ah[a];

    const int tid = threadIdx.x;
    const int j0 = tid;
    const int j1 = tid + THREADS;
    const int j2 = tid + 2 * THREADS;
    const int j3 = tid + 3 * THREADS;
    const int j4 = tid + 4 * THREADS;          // valid only for tid < 81
    const bool tail = (j4 < NV);

    // Issue all loads back-to-back (MLP = 5 per thread).
    #define SRCIDX(j) ((j) / QV * GGV + ((j) - (j) / QV * QV))
    const float4 v0 = src[SRCIDX(j0)];
    const float4 v1 = src[SRCIDX(j1)];
    const float4 v2 = src[SRCIDX(j2)];
    const float4 v3 = src[SRCIDX(j3)];
    float4 v4 = make_float4(0.f, 0.f, 0.f, 0.f);
    if (tail) v4 = src[SRCIDX(j4)];
    #undef SRCIDX

    transform_store(s, v0, j0, p0, aw, ah);
    transform_store(s, v1, j1, p0, aw, ah);
    transform_store(s, v2, j2, p0, aw, ah);
    transform_store(s, v3, j3, p0, aw, ah);
    if (tail) transform_store(s, v4, j4, p0, aw, ah);

    __syncthreads();

    // Phase 2: tile's output is one contiguous span of TILE*NE = 4420 floats.
    // Default cache policy (A/B vs __stcs).
    float4* __restrict__ dst =
        reinterpret_cast<float4*>(out + (size_t)t * (TILE * NE));
    const float4* __restrict__ ss = reinterpret_cast<const float4*>(s);
    dst[j0] = ss[j0];
    dst[j1] = ss[j1];
    dst[j2] = ss[j2];
    dst[j3] = ss[j3];
    if (tail) dst[j4] = ss[j4];
}

extern "C" void kernel_launch(void* const* d_in, const int* in_sizes, int n_in,
                              void* d_out, int out_size) {
    const float* x = (const float*)d_in[0];
    float* out = (float*)d_out;
    const int blocks = out_size / (TILE * NE);   // 9984
    det_decode_kernel<<<blocks, THREADS>>>(x, out);
}